// round 4
// baseline (speedup 1.0000x reference)
#include <cuda_runtime.h>

typedef unsigned long long ull;

#define TINYF 1e-6f
#define PIF   3.14159265358979323846f

// Per-lobe packed constants, SoA [kpair][l]. All a/b/c pre-scaled by |u_k|, u = W2/4.
__device__ ull   g_na2[8 * 128];   // (|u|*-a) pairs
__device__ ull   g_nb2[8 * 128];   // (|u|*-b) pairs
__device__ ull   g_nc2[8 * 128];   // (|u|*-c) pairs
__device__ float g_A[3 * 128];     // U*sinphi
__device__ float g_B[3 * 128];     // V*sinphi
__device__ float g_C[3 * 128];     // l*cosphi
__device__ float g_w[128];         // exp(sharp*(cosphi-1))
__device__ float g_Ap[128];        // sum_k u_k * (-a_kl)   (signed u)
__device__ float g_Bp[128];        // sum_k u_k * (-b_kl)
__device__ float g_Cp[128];        // sum_k u_k * (-c_kl)
__device__ ull   g_sg2[8];         // (sgn(u_2k), sgn(u_2k+1)) as +-1.0f
__device__ ull   g_au2[8];         // (|u_2k|, |u_2k+1|)
__device__ float g_u[16];          // signed u_k

__device__ __forceinline__ ull pack2(float x, float y) {
    ull r; asm("mov.b64 %0, {%1, %2};" : "=l"(r) : "f"(x), "f"(y)); return r;
}
__device__ __forceinline__ void unpack2(ull v, float& x, float& y) {
    asm("mov.b64 {%0, %1}, %2;" : "=f"(x), "=f"(y) : "l"(v));
}
__device__ __forceinline__ ull fma2(ull a, ull b, ull c) {
    ull d; asm("fma.rn.f32x2 %0, %1, %2, %3;" : "=l"(d) : "l"(a), "l"(b), "l"(c)); return d;
}
__device__ __forceinline__ ull add2(ull a, ull b) {
    ull d; asm("add.rn.f32x2 %0, %1, %2;" : "=l"(d) : "l"(a), "l"(b)); return d;
}
__device__ __forceinline__ ull mul2(ull a, ull b) {
    ull d; asm("mul.rn.f32x2 %0, %1, %2;" : "=l"(d) : "l"(a), "l"(b)); return d;
}
__device__ __forceinline__ float tanh_fast(float x) {
    float y; asm("tanh.approx.f32 %0, %1;" : "=f"(y) : "f"(x)); return y;
}

__global__ void precompute_kernel(const float* __restrict__ lobes,
                                  const float* __restrict__ lambdas,
                                  const float* __restrict__ rot,
                                  const float* __restrict__ W1,
                                  const float* __restrict__ W2) {
    __shared__ float sM[3][16];   // M = root_rot @ W1[3:6]
    __shared__ float su[16];      // signed u = W2/4
    __shared__ float sau[16];     // |u|
    int t = threadIdx.x;
    if (t < 48) {
        int d = t >> 4, k = t & 15;
        sM[d][k] = rot[d * 3 + 0] * W1[3 * 16 + k]
                 + rot[d * 3 + 1] * W1[4 * 16 + k]
                 + rot[d * 3 + 2] * W1[5 * 16 + k];
    }
    if (t < 16) {
        float u = 0.25f * W2[t];
        su[t] = u; sau[t] = fabsf(u);
    }
    __syncthreads();

    int l = t;  // blockDim.x == 128
    float lx = lobes[l * 3 + 0], ly = lobes[l * 3 + 1], lz = lobes[l * 3 + 2];
    float inv = 1.f / (sqrtf(lx * lx + ly * ly + lz * lz) + TINYF);
    lx *= inv; ly *= inv; lz *= inv;

    float ux = -ly, uy = lx, uz = 0.f;
    float invu = 1.f / (sqrtf(ux * ux + uy * uy) + TINYF);
    ux *= invu; uy *= invu;

    float vx = ly * uz - lz * uy;
    float vy = lz * ux - lx * uz;
    float vz = lx * uy - ly * ux;
    float invv = 1.f / (sqrtf(vx * vx + vy * vy + vz * vz) + TINYF);
    vx *= invv; vy *= invv; vz *= invv;

    float sharp = lambdas[l];
    float rphi  = fminf(acosf(1.f - 1.f / sharp), PIF / 3.f);
    float sp = sinf(rphi), cp = cosf(rphi);

    float Ax = ux * sp, Ay = uy * sp, Az = uz * sp;
    float Bx = vx * sp, By = vy * sp, Bz = vz * sp;
    float Cx = lx * cp, Cy = ly * cp, Cz = lz * cp;

    g_A[l] = Ax; g_A[128 + l] = Ay; g_A[256 + l] = Az;
    g_B[l] = Bx; g_B[128 + l] = By; g_B[256 + l] = Bz;
    g_C[l] = Cx; g_C[128 + l] = Cy; g_C[256 + l] = Cz;
    g_w[l] = expf(sharp * (cp - 1.f));

    float na[16], nb[16], nc[16];
#pragma unroll
    for (int k = 0; k < 16; k++) {
        na[k] = -(Ax * sM[0][k] + Ay * sM[1][k] + Az * sM[2][k]);
        nb[k] = -(Bx * sM[0][k] + By * sM[1][k] + Bz * sM[2][k]);
        nc[k] = -(Cx * sM[0][k] + Cy * sM[1][k] + Cz * sM[2][k]);
    }

    float Ap = 0.f, Bp = 0.f, Cp = 0.f;
#pragma unroll
    for (int k = 0; k < 16; k++) {
        Ap = fmaf(su[k], na[k], Ap);
        Bp = fmaf(su[k], nb[k], Bp);
        Cp = fmaf(su[k], nc[k], Cp);
    }
    g_Ap[l] = Ap; g_Bp[l] = Bp; g_Cp[l] = Cp;

#pragma unroll
    for (int kp = 0; kp < 8; kp++) {
        int k0 = 2 * kp, k1 = 2 * kp + 1;
        g_na2[kp * 128 + l] = pack2(sau[k0] * na[k0], sau[k1] * na[k1]);
        g_nb2[kp * 128 + l] = pack2(sau[k0] * nb[k0], sau[k1] * nb[k1]);
        g_nc2[kp * 128 + l] = pack2(sau[k0] * nc[k0], sau[k1] * nc[k1]);
    }
    if (l < 8) {
        g_sg2[l] = pack2(su[2 * l] >= 0.f ? 1.f : -1.f,
                         su[2 * l + 1] >= 0.f ? 1.f : -1.f);
        g_au2[l] = pack2(sau[2 * l], sau[2 * l + 1]);
    }
    if (l < 16) g_u[l] = su[l];
}

// One block per point n (128 threads = 128 lobes), S=8 samples per thread.
__global__ __launch_bounds__(128) void vis_kernel(
    const float* __restrict__ points,
    const float* __restrict__ normals,
    const float* __restrict__ r,       // (N, 128, 8)
    const float* __restrict__ W1,      // (6, 16)
    const float* __restrict__ b1,      // (16,)
    const float* __restrict__ W2,      // (16, 1)  (unused; folded)
    const float* __restrict__ b2,      // (1,)
    float* __restrict__ out)           // (N, 128)
{
    const int n = blockIdx.x;
    const int l = threadIdx.x;

    __shared__ float s_base[16];   // points[n] @ W1[:3] + b1
    __shared__ ull   s_b2q[8];     // |u|-scaled packed base pairs
    __shared__ float s_nrm[3];
    __shared__ float s_lin0;       // b2/2 + sum_k u_k * base_k   (signed u)

    if (l < 16) {
        float px = points[n * 3 + 0], py = points[n * 3 + 1], pz = points[n * 3 + 2];
        s_base[l] = fmaf(px, W1[0 * 16 + l],
                    fmaf(py, W1[1 * 16 + l],
                    fmaf(pz, W1[2 * 16 + l], b1[l])));
    }
    if (l < 3) s_nrm[l] = normals[n * 3 + l];
    __syncthreads();

    if (l == 0) {
        float c1 = 0.5f * b2[0];
#pragma unroll
        for (int k = 0; k < 16; k++) c1 = fmaf(g_u[k], s_base[k], c1);
        s_lin0 = c1;
    }
    if (l < 8) s_b2q[l] = mul2(pack2(s_base[2 * l], s_base[2 * l + 1]), g_au2[l]);
    __syncthreads();

    // Per-(n,l) scalars
    const float nx = s_nrm[0], ny = s_nrm[1], nz = s_nrm[2];
    const float an = fmaf(g_A[l], nx, fmaf(g_A[128 + l], ny, g_A[256 + l] * nz));
    const float bn = fmaf(g_B[l], nx, fmaf(g_B[128 + l], ny, g_B[256 + l] * nz));
    const float cn = fmaf(g_C[l], nx, fmaf(g_C[128 + l], ny, g_C[256 + l] * nz));
    const float wl = g_w[l];
    const float Ap = g_Ap[l], Bp = g_Bp[l];
    const float linl = s_lin0 + g_Cp[l];

    // Packed per-lobe MLP constants (registers across all samples)
    ull na2[8], nb2[8], b22[8], sg2[8];
#pragma unroll
    for (int kp = 0; kp < 8; kp++) {
        na2[kp] = g_na2[kp * 128 + l];
        nb2[kp] = g_nb2[kp * 128 + l];
        b22[kp] = add2(s_b2q[kp], g_nc2[kp * 128 + l]);
        sg2[kp] = g_sg2[kp];            // uniform -> URs
    }

    const float* rbase = r + (size_t)(n * 128 + l) * 8;

    float vsum = 0.f;
#pragma unroll
    for (int chunk = 0; chunk < 2; chunk++) {
        const float4 rv = *reinterpret_cast<const float4*>(rbase + chunk * 4);
        float rr[4] = {rv.x, rv.y, rv.z, rv.w};
#pragma unroll
        for (int j = 0; j < 4; j++) {
            const int s = chunk * 4 + j;
            float theta = (rr[j] + (float)s) * (PIF * 0.25f);
            float st, ct;
            __sincosf(theta, &st, &ct);

            float cosn = fmaf(ct, an, fmaf(st, bn, cn));

            ull ct2 = pack2(ct, ct);
            ull st2 = pack2(st, st);

            ull acc2 = 0ULL;
#pragma unroll
            for (int kp = 0; kp < 8; kp++) {
                ull h2 = fma2(ct2, na2[kp], fma2(st2, nb2[kp], b22[kp]));
                ull habs2 = h2 & 0x7fffffff7fffffffULL;   // 2x LOP3, alu pipe
                acc2 = fma2(habs2, sg2[kp], acc2);
            }
            float a0, a1;
            unpack2(acc2, a0, a1);

            // P/2 = linear part + sum sgn*|h'|
            float logit = fmaf(ct, Ap, fmaf(st, Bp, linl)) + a0 + a1;
            float vis = fmaf(tanh_fast(logit), 0.5f, 0.5f);
            vsum += (cosn > TINYF) ? vis : 0.f;
        }
    }

    out[n * 128 + l] = __fdividef(wl * vsum, 8.f * wl + TINYF);
}

extern "C" void kernel_launch(void* const* d_in, const int* in_sizes, int n_in,
                              void* d_out, int out_size) {
    const float* points  = (const float*)d_in[0];
    const float* normals = (const float*)d_in[1];
    const float* rot     = (const float*)d_in[2];
    const float* lobes   = (const float*)d_in[3];
    const float* lambdas = (const float*)d_in[4];
    const float* r       = (const float*)d_in[5];
    const float* W1      = (const float*)d_in[6];
    const float* b1      = (const float*)d_in[7];
    const float* W2      = (const float*)d_in[8];
    const float* b2      = (const float*)d_in[9];

    const int N = in_sizes[0] / 3;   // 8192

    precompute_kernel<<<1, 128>>>(lobes, lambdas, rot, W1, W2);
    vis_kernel<<<N, 128>>>(points, normals, r, W1, b1, W2, b2, (float*)d_out);
}

// round 5
// speedup vs baseline: 1.1101x; 1.1101x over previous
#include <cuda_runtime.h>

typedef unsigned long long ull;

#define TINYF 1e-6f
#define PIF   3.14159265358979323846f
#define NPER  4

// Per-lobe constants (L=128, H=16). Pairs (2k,2k+1), SoA [kpair][l]. na = -a, etc.
__device__ ull   g_na2[8 * 128];
__device__ ull   g_nb2[8 * 128];
__device__ ull   g_nc2[8 * 128];
__device__ float g_A[3 * 128];     // U*sinphi
__device__ float g_B[3 * 128];     // V*sinphi
__device__ float g_C[3 * 128];     // l*cosphi
__device__ float g_w[128];         // exp(sharp*(cosphi-1))
__device__ float g_Ap[128];        // sum_k u_k * na_kl   (u = W2/4, signed)
__device__ float g_Bp[128];        // sum_k u_k * nb_kl
__device__ float g_Cp[128];        // sum_k u_k * nc_kl
__device__ float g_u[16];          // u_k = W2_k / 4

__device__ __forceinline__ ull pack2(float x, float y) {
    ull r; asm("mov.b64 %0, {%1, %2};" : "=l"(r) : "f"(x), "f"(y)); return r;
}
__device__ __forceinline__ void unpack2(ull v, float& x, float& y) {
    asm("mov.b64 {%0, %1}, %2;" : "=f"(x), "=f"(y) : "l"(v));
}
__device__ __forceinline__ ull fma2(ull a, ull b, ull c) {
    ull d; asm("fma.rn.f32x2 %0, %1, %2, %3;" : "=l"(d) : "l"(a), "l"(b), "l"(c)); return d;
}
__device__ __forceinline__ ull add2(ull a, ull b) {
    ull d; asm("add.rn.f32x2 %0, %1, %2;" : "=l"(d) : "l"(a), "l"(b)); return d;
}
__device__ __forceinline__ float tanh_fast(float x) {
    float y; asm("tanh.approx.f32 %0, %1;" : "=f"(y) : "f"(x)); return y;
}

__global__ void precompute_kernel(const float* __restrict__ lobes,
                                  const float* __restrict__ lambdas,
                                  const float* __restrict__ rot,
                                  const float* __restrict__ W1,
                                  const float* __restrict__ W2) {
    __shared__ float sM[3][16];   // M = root_rot @ W1[3:6]
    __shared__ float su[16];      // u = W2/4 (signed)
    int t = threadIdx.x;
    if (t < 48) {
        int d = t >> 4, k = t & 15;
        sM[d][k] = rot[d * 3 + 0] * W1[3 * 16 + k]
                 + rot[d * 3 + 1] * W1[4 * 16 + k]
                 + rot[d * 3 + 2] * W1[5 * 16 + k];
    }
    if (t < 16) su[t] = 0.25f * W2[t];
    __syncthreads();

    int l = t;  // blockDim.x == 128
    float lx = lobes[l * 3 + 0], ly = lobes[l * 3 + 1], lz = lobes[l * 3 + 2];
    float inv = 1.f / (sqrtf(lx * lx + ly * ly + lz * lz) + TINYF);
    lx *= inv; ly *= inv; lz *= inv;

    float ux = -ly, uy = lx, uz = 0.f;
    float invu = 1.f / (sqrtf(ux * ux + uy * uy) + TINYF);
    ux *= invu; uy *= invu;

    float vx = ly * uz - lz * uy;
    float vy = lz * ux - lx * uz;
    float vz = lx * uy - ly * ux;
    float invv = 1.f / (sqrtf(vx * vx + vy * vy + vz * vz) + TINYF);
    vx *= invv; vy *= invv; vz *= invv;

    float sharp = lambdas[l];
    float rphi  = fminf(acosf(1.f - 1.f / sharp), PIF / 3.f);
    float sp = sinf(rphi), cp = cosf(rphi);

    float Ax = ux * sp, Ay = uy * sp, Az = uz * sp;
    float Bx = vx * sp, By = vy * sp, Bz = vz * sp;
    float Cx = lx * cp, Cy = ly * cp, Cz = lz * cp;

    g_A[l] = Ax; g_A[128 + l] = Ay; g_A[256 + l] = Az;
    g_B[l] = Bx; g_B[128 + l] = By; g_B[256 + l] = Bz;
    g_C[l] = Cx; g_C[128 + l] = Cy; g_C[256 + l] = Cz;
    g_w[l] = expf(sharp * (cp - 1.f));

    float na[16], nb[16], nc[16];
#pragma unroll
    for (int k = 0; k < 16; k++) {
        na[k] = -(Ax * sM[0][k] + Ay * sM[1][k] + Az * sM[2][k]);
        nb[k] = -(Bx * sM[0][k] + By * sM[1][k] + Bz * sM[2][k]);
        nc[k] = -(Cx * sM[0][k] + Cy * sM[1][k] + Cz * sM[2][k]);
    }

    float Ap = 0.f, Bp = 0.f, Cp = 0.f;
#pragma unroll
    for (int k = 0; k < 16; k++) {
        Ap = fmaf(su[k], na[k], Ap);
        Bp = fmaf(su[k], nb[k], Bp);
        Cp = fmaf(su[k], nc[k], Cp);
    }
    g_Ap[l] = Ap; g_Bp[l] = Bp; g_Cp[l] = Cp;

#pragma unroll
    for (int kp = 0; kp < 8; kp++) {
        g_na2[kp * 128 + l] = pack2(na[2 * kp], na[2 * kp + 1]);
        g_nb2[kp * 128 + l] = pack2(nb[2 * kp], nb[2 * kp + 1]);
        g_nc2[kp * 128 + l] = pack2(nc[2 * kp], nc[2 * kp + 1]);
    }
    if (l < 16) g_u[l] = su[l];
}

// One block handles NPER points (128 threads = 128 lobes each).
__global__ __launch_bounds__(128) void vis_kernel(
    const float* __restrict__ points,
    const float* __restrict__ normals,
    const float* __restrict__ r,       // (N, 128, 8)
    const float* __restrict__ W1,      // (6, 16)
    const float* __restrict__ b1,      // (16,)
    const float* __restrict__ W2,      // (16, 1)  (folded)
    const float* __restrict__ b2,      // (1,)
    float* __restrict__ out)           // (N, 128)
{
    const int n0 = blockIdx.x * NPER;
    const int l  = threadIdx.x;

    __shared__ float s_base[NPER][16];   // points[n] @ W1[:3] + b1
    __shared__ ull   s_basep[NPER][8];   // packed pairs
    __shared__ float s_nrm[NPER][3];
    __shared__ float s_lin0[NPER];       // b2/2 + sum_k u_k*base_k

    if (l < 16 * NPER) {
        int i = l >> 4, k = l & 15;
        int n = n0 + i;
        float px = points[n * 3 + 0], py = points[n * 3 + 1], pz = points[n * 3 + 2];
        s_base[i][k] = fmaf(px, W1[0 * 16 + k],
                       fmaf(py, W1[1 * 16 + k],
                       fmaf(pz, W1[2 * 16 + k], b1[k])));
    }
    if (l >= 64 && l < 64 + 3 * NPER) {
        int j = l - 64;
        s_nrm[j / 3][j % 3] = normals[(n0 + j / 3) * 3 + (j % 3)];
    }
    __syncthreads();

    if (l < NPER) {
        float c1 = 0.5f * b2[0];
#pragma unroll
        for (int k = 0; k < 16; k++) c1 = fmaf(g_u[k], s_base[l][k], c1);
        s_lin0[l] = c1;
    }
    if (l < 8 * NPER) {
        int i = l >> 3, kp = l & 7;
        s_basep[i][kp] = pack2(s_base[i][2 * kp], s_base[i][2 * kp + 1]);
    }
    __syncthreads();

    // ---- Per-lobe persistent state (reused across all NPER points) ----
    ull na2[8], nb2[8];
    float u[16];
#pragma unroll
    for (int kp = 0; kp < 8; kp++) {
        na2[kp] = g_na2[kp * 128 + l];
        nb2[kp] = g_nb2[kp * 128 + l];
    }
#pragma unroll
    for (int k = 0; k < 16; k++) u[k] = g_u[k];

    const float wl = g_w[l];
    const float Ap = g_Ap[l], Bp = g_Bp[l], Cp = g_Cp[l];

    // Normal-gate coefficients for all NPER points (then basis regs die)
    float an[NPER], bn[NPER], cn[NPER];
    {
        float A0 = g_A[l], A1 = g_A[128 + l], A2 = g_A[256 + l];
        float B0 = g_B[l], B1 = g_B[128 + l], B2 = g_B[256 + l];
        float C0 = g_C[l], C1 = g_C[128 + l], C2 = g_C[256 + l];
#pragma unroll
        for (int i = 0; i < NPER; i++) {
            float nx = s_nrm[i][0], ny = s_nrm[i][1], nz = s_nrm[i][2];
            an[i] = fmaf(A0, nx, fmaf(A1, ny, A2 * nz));
            bn[i] = fmaf(B0, nx, fmaf(B1, ny, B2 * nz));
            cn[i] = fmaf(C0, nx, fmaf(C1, ny, C2 * nz));
        }
    }

    const float owl = __fdividef(wl, 8.f * wl + TINYF);

#pragma unroll
    for (int i = 0; i < NPER; i++) {
        const int n = n0 + i;
        const float lin = s_lin0[i] + Cp;
        const float ani = an[i], bni = bn[i], cni = cn[i];

        // b22 for this point: shared base pairs + L1-hot nc2 table
        ull b22[8];
#pragma unroll
        for (int kp = 0; kp < 8; kp++)
            b22[kp] = add2(s_basep[i][kp], g_nc2[kp * 128 + l]);

        const float* rbase = r + (size_t)(n * 128 + l) * 8;

        float vsum = 0.f;
#pragma unroll
        for (int chunk = 0; chunk < 2; chunk++) {
            const float4 rv = *reinterpret_cast<const float4*>(rbase + chunk * 4);
            float rr[4] = {rv.x, rv.y, rv.z, rv.w};
#pragma unroll
            for (int j = 0; j < 4; j++) {
                const int s = chunk * 4 + j;
                float theta = (rr[j] + (float)s) * (PIF * 0.25f);
                float st, ct;
                __sincosf(theta, &st, &ct);

                float cosn = fmaf(ct, ani, fmaf(st, bni, cni));

                ull ct2 = pack2(ct, ct);
                ull st2 = pack2(st, st);

                float acc0 = 0.f, acc1 = 0.f;
#pragma unroll
                for (int kp = 0; kp < 8; kp++) {
                    ull h2 = fma2(ct2, na2[kp], fma2(st2, nb2[kp], b22[kp]));
                    float hlo, hhi;
                    unpack2(h2, hlo, hhi);
                    acc0 = fmaf(fabsf(hlo), u[2 * kp + 0], acc0);   // |src| folds into FFMA
                    acc1 = fmaf(fabsf(hhi), u[2 * kp + 1], acc1);
                }
                // half-logit = linear part + sum u*|h|
                float logit = fmaf(ct, Ap, fmaf(st, Bp, lin)) + acc0 + acc1;
                float vis = fmaf(tanh_fast(logit), 0.5f, 0.5f);
                vsum += (cosn > TINYF) ? vis : 0.f;
            }
        }

        out[n * 128 + l] = owl * vsum;
    }
}

extern "C" void kernel_launch(void* const* d_in, const int* in_sizes, int n_in,
                              void* d_out, int out_size) {
    const float* points  = (const float*)d_in[0];
    const float* normals = (const float*)d_in[1];
    const float* rot     = (const float*)d_in[2];
    const float* lobes   = (const float*)d_in[3];
    const float* lambdas = (const float*)d_in[4];
    const float* r       = (const float*)d_in[5];
    const float* W1      = (const float*)d_in[6];
    const float* b1      = (const float*)d_in[7];
    const float* W2      = (const float*)d_in[8];
    const float* b2      = (const float*)d_in[9];

    const int N = in_sizes[0] / 3;   // 8192

    precompute_kernel<<<1, 128>>>(lobes, lambdas, rot, W1, W2);
    vis_kernel<<<N / NPER, 128>>>(points, normals, r, W1, b1, W2, b2, (float*)d_out);
}